// round 6
// baseline (speedup 1.0000x reference)
#include <cuda_runtime.h>
#include <math.h>

#define BB 32768
#define EE 9
#define RANKK 50
#define DD 450            // E*RANK
#define WPB 8             // warps per block (4 pairs)
#define NB 444            // persistent grid: 148 SMs x 3 blocks
#define NBP 448           // padded partial stride (pad slots stay zero)
#define TOTW (NB * WPB)   // 3552 warps
#define XOFF 2            // head starts at sxw[2] so rel (sxw[452]) is 16B-aligned
#define XSZ 1352          // 2 + 450 + 900

// per-block partials: [v*NBP + block], v = 0..8 load, 9..17 importance
__device__ float g_part[18 * NBP];
__device__ unsigned int g_count = 0;

__device__ __forceinline__ float softplusf(float x) {
    if (x > 20.0f) return x;
    return log1pf(expf(x));
}
__device__ __forceinline__ float phif(float z) {
    return 0.5f * (1.0f + erff(z * 0.70710678118654752f));
}

__global__ __launch_bounds__(256, 3) void swise_main_kernel(
    const int* __restrict__ queries, const int* __restrict__ these_queries,
    const float* __restrict__ entity, const float* __restrict__ rel,
    const float* __restrict__ rel_diag,
    const float* __restrict__ bh, const float* __restrict__ bt,
    const float* __restrict__ c_param,
    const float* __restrict__ cnn_w, const float* __restrict__ cnn_b,
    const float* __restrict__ h2e_w, const float* __restrict__ h2e_b,
    const float* __restrict__ cnnn_w, const float* __restrict__ cnnn_b,
    const float* __restrict__ h2en_w, const float* __restrict__ h2en_b,
    const float* __restrict__ noise, float* __restrict__ y_out, int loss_idx)
{
    __shared__ __align__(16) float sx[WPB][XSZ];     // x image per warp
    __shared__ __align__(16) float xacc[WPB][128];   // activation exchange
    __shared__ float xres[WPB][12];                  // 9-float result exchange
    __shared__ float swc[25], swn[25];
    __shared__ float sbc[2];
    __shared__ float sbe[EE], sben[EE];
    __shared__ float s_load[EE], s_imp[EE];
    __shared__ unsigned int s_is_last;
    __shared__ double totals[18];

    const int tid = threadIdx.x;
    for (int i = tid; i < 25; i += blockDim.x) { swc[i] = cnn_w[i]; swn[i] = cnnn_w[i]; }
    if (tid == 0) { sbc[0] = cnn_b[0]; sbc[1] = cnnn_b[0]; }
    if (tid < EE) { sbe[tid] = h2e_b[tid]; sben[tid] = h2en_b[tid];
                    s_load[tid] = 0.0f; s_imp[tid] = 0.0f; }
    __syncthreads();

    const int warp = tid >> 5, lane = tid & 31;
    const int ly = lane >> 2;          // oh  (0..7)
    const int lx = lane & 3;           // ow group (0..3), ow = 4*lx + q
    const int f_base = 16 * ly + 4 * lx;
    const int role = warp & 1;         // 0: owns clean weights, 1: owns stdv weights
    const int bid = 1 + (warp >> 1);   // named barrier per pair
    float* sxw = sx[warp];
    const int gw = blockIdx.x * WPB + warp;

    // register-resident linear weights (loaded once)
    float4 wreg[EE];
    {
        const float4* wsrc = (const float4*)(role ? h2en_w : h2e_w);
        #pragma unroll
        for (int e = 0; e < EE; e++)
            wreg[e] = __ldg(wsrc + e * 32 + (f_base >> 2));
    }

    for (int b = gw; b < BB; b += TOTW) {
        const int q0 = queries[3 * b];
        const int q1 = queries[3 * b + 1];
        const int t2 = these_queries[3 * b + 2];

        __syncwarp();   // WAR: previous iteration's reads of sxw done

        // ---- stage x = [head | rel] contiguous at sxw+XOFF ----
        const float2* hrow = (const float2*)(entity + (size_t)q0 * DD);
        #pragma unroll
        for (int t = 0; t < 8; t++) {
            const int i = lane + 32 * t;
            if (i < 225) {
                const float2 v = __ldg(hrow + i);
                *(float2*)&sxw[XOFF + 2 * i] = v;
            }
        }
        const float4* rrow = (const float4*)(rel + (size_t)q1 * (2 * DD));
        #pragma unroll
        for (int t = 0; t < 8; t++) {
            const int i = lane + 32 * t;
            if (i < 225) {
                const float4 v = __ldg(rrow + i);
                *(float4*)&sxw[XOFF + DD + 4 * i] = v;
            }
        }
        __syncwarp();

        // ---- conv (stride 3, VALID): each lane computes 4 consecutive ow ----
        float accc[4] = {0.f, 0.f, 0.f, 0.f};
        float accn[4] = {0.f, 0.f, 0.f, 0.f};
        #pragma unroll
        for (int kh = 0; kh < 5; kh++) {
            const float* rp = sxw + XOFF + (3 * ly + kh) * RANKK + 12 * lx;
            float row[14];
            #pragma unroll
            for (int j2 = 0; j2 < 7; j2++) {
                const float2 t = *(const float2*)(rp + 2 * j2);
                row[2 * j2] = t.x; row[2 * j2 + 1] = t.y;
            }
            #pragma unroll
            for (int kw = 0; kw < 5; kw++) {
                const float wc = swc[kh * 5 + kw], wn = swn[kh * 5 + kw];
                #pragma unroll
                for (int q = 0; q < 4; q++) {
                    const float xv = row[3 * q + kw];
                    accc[q] = fmaf(xv, wc, accc[q]);
                    accn[q] = fmaf(xv, wn, accn[q]);
                }
            }
        }
        #pragma unroll
        for (int q = 0; q < 4; q++) { accc[q] += sbc[0]; accn[q] += sbc[1]; }

        // ---- pair exchange: ship the acc this warp does NOT weight ----
        {
            const float4 outv = role
                ? make_float4(accc[0], accc[1], accc[2], accc[3])
                : make_float4(accn[0], accn[1], accn[2], accn[3]);
            *(float4*)&xacc[warp][f_base] = outv;
        }
        asm volatile("bar.sync %0, 64;" :: "r"(bid));
        const float4 pac = *(const float4*)&xacc[warp ^ 1][f_base];
        const float o0 = role ? accn[0] : accc[0];
        const float o1 = role ? accn[1] : accc[1];
        const float o2 = role ? accn[2] : accc[2];
        const float o3 = role ? accn[3] : accc[3];

        // ---- apply register weights to own + partner element, route+reduce ----
        const bool lowh = (lane < 16);
        float val[EE];
        #pragma unroll
        for (int e = 0; e < EE; e++) {
            float po = o0 * wreg[e].x; po = fmaf(o1, wreg[e].y, po);
            po = fmaf(o2, wreg[e].z, po); po = fmaf(o3, wreg[e].w, po);
            float pp = pac.x * wreg[e].x; pp = fmaf(pac.y, wreg[e].y, pp);
            pp = fmaf(pac.z, wreg[e].z, pp); pp = fmaf(pac.w, wreg[e].w, pp);
            const float oc = __shfl_xor_sync(0xffffffffu, po, 16);
            const float op = __shfl_xor_sync(0xffffffffu, pp, 16);
            val[e] = lowh ? (po + oc) : (pp + op);
        }
        #pragma unroll
        for (int off = 8; off > 0; off >>= 1) {
            #pragma unroll
            for (int e = 0; e < EE; e++)
                val[e] += __shfl_xor_sync(0xffffffffu, val[e], off);
        }
        // upper half holds partner-element sums -> publish for partner warp
        #pragma unroll
        for (int e = 0; e < EE; e++)
            if (lane == 16 + e) xres[warp][e] = val[e];
        // broadcast own-element sums (in lower half) to all lanes
        float ownv[EE];
        #pragma unroll
        for (int e = 0; e < EE; e++) {
            const float t = __shfl_xor_sync(0xffffffffu, val[e], 16);
            ownv[e] = lowh ? val[e] : t;
        }
        asm volatile("bar.sync %0, 64;" :: "r"(bid));

        // ---- merge: clean from even warp, stdv from odd warp ----
        float clean[EE], stdv[EE];
        #pragma unroll
        for (int e = 0; e < EE; e++) {
            const float oth = xres[warp ^ 1][e];
            clean[e] = role ? oth : ownv[e];
            stdv[e]  = role ? ownv[e] : oth;
        }

        // ---- gating (uniform across lanes) ----
        float noisyv[EE];
        #pragma unroll
        for (int e = 0; e < EE; e++) {
            clean[e] += sbe[e];
            stdv[e] = softplusf(stdv[e] + sben[e]) + 0.01f;
            noisyv[e] = fmaf(noise[(size_t)b * EE + e], stdv[e], clean[e]);
        }
        int i1 = 0; float v1 = noisyv[0];
        #pragma unroll
        for (int e = 1; e < EE; e++) if (noisyv[e] > v1) { v1 = noisyv[e]; i1 = e; }
        int i2 = -1; float v2 = -INFINITY;
        #pragma unroll
        for (int e = 0; e < EE; e++) if (e != i1 && noisyv[e] > v2) { v2 = noisyv[e]; i2 = e; }
        float v3 = -INFINITY;
        #pragma unroll
        for (int e = 0; e < EE; e++) if (e != i1 && e != i2 && noisyv[e] > v3) v3 = noisyv[e];

        const float t_e = expf(v2 - v1);
        const float g1 = 1.0f / (1.0f + t_e);
        const float g2 = t_e / (1.0f + t_e);

        // prob/load: one expert per lane (parallel erf, conflict-free atomics)
        if (lane < EE) {
            float ce = 0.0f, se = 1.0f, ne = 0.0f;
            #pragma unroll
            for (int e = 0; e < EE; e++)
                if (lane == e) { ce = clean[e]; se = stdv[e]; ne = noisyv[e]; }
            const float thr = (ne > v3) ? v3 : v2;
            atomicAdd(&s_load[lane], phif((ce - thr) / se));
        }
        if (lane == 0) {
            atomicAdd(&s_imp[i1], g1);
            if (g2 > 0.0f) atomicAdd(&s_imp[i2], g2);
        }

        // ---- Givens + distance, ONLY for experts i1 and i2 (50 pairs) ----
        const float* rd = rel_diag + (size_t)q1 * DD;
        const float* rh = entity + (size_t)t2 * DD;
        float dA = 0.0f, dB = 0.0f;    // d2[i1], d2[i2]

        {   // item 1: lanes 0..24 -> expert i1, lanes 25..31 -> expert i2
            const bool sel = lane < 25;
            const int e = sel ? i1 : i2;
            const int p = sel ? lane : lane - 25;
            const float2 r2 = __ldg((const float2*)(rd + e * RANKK) + p);
            const float2 h2v = __ldg((const float2*)(rh + e * RANKK) + p);
            const float inv = rsqrtf(fmaxf(r2.x * r2.x + r2.y * r2.y, 1e-30f));
            const float c0 = r2.x * inv, c1 = r2.y * inv;
            const float x0 = sxw[XOFF + e * RANKK + 2 * p];
            const float x1 = sxw[XOFF + e * RANKK + 2 * p + 1];
            const float rl0 = sxw[XOFF + DD + e * (2 * RANKK) + 2 * p];
            const float rl1 = sxw[XOFF + DD + e * (2 * RANKK) + 2 * p + 1];
            const float u0 = (c0 * x0 - c1 * x1) + rl0 - h2v.x;
            const float u1 = (c1 * x0 + c0 * x1) + rl1 - h2v.y;
            const float dd = fmaf(u0, u0, u1 * u1);
            if (sel) dA += dd; else dB += dd;
        }
        if (lane < 18) {  // item 2: expert i2, p = lane+7
            const int p = lane + 7;
            const int e = i2;
            const float2 r2 = __ldg((const float2*)(rd + e * RANKK) + p);
            const float2 h2v = __ldg((const float2*)(rh + e * RANKK) + p);
            const float inv = rsqrtf(fmaxf(r2.x * r2.x + r2.y * r2.y, 1e-30f));
            const float c0 = r2.x * inv, c1 = r2.y * inv;
            const float x0 = sxw[XOFF + e * RANKK + 2 * p];
            const float x1 = sxw[XOFF + e * RANKK + 2 * p + 1];
            const float rl0 = sxw[XOFF + DD + e * (2 * RANKK) + 2 * p];
            const float rl1 = sxw[XOFF + DD + e * (2 * RANKK) + 2 * p + 1];
            const float u0 = (c0 * x0 - c1 * x1) + rl0 - h2v.x;
            const float u1 = (c1 * x0 + c0 * x1) + rl1 - h2v.y;
            dB = fmaf(u0, u0, fmaf(u1, u1, dB));
        }
        #pragma unroll
        for (int off = 16; off > 0; off >>= 1) {
            dA += __shfl_xor_sync(0xffffffffu, dA, off);
            dB += __shfl_xor_sync(0xffffffffu, dB, off);
        }

        // ---- score + masked logsumexp (mask = top-2 gates > 0) ----
        if (lane == 0) {
            const float cc = softplusf(c_param[q1]);
            const float bsum = bh[q0] + bt[t2];
            const float sc1 = bsum - cc * dA;
            const float sc2 = bsum - cc * dB;
            float s = expf(sc1) + (g2 > 0.0f ? expf(sc2) : 0.0f);
            if (s == 0.0f) s = 2.220446049250313e-16f;
            y_out[b] = logf(s);
        }
    }

    __syncthreads();
    if (tid < EE)       g_part[tid * NBP + blockIdx.x] = s_load[tid];
    else if (tid < 18)  g_part[tid * NBP + blockIdx.x] = s_imp[tid - 9];
    __threadfence();
    if (tid == 0) {
        const unsigned int c = atomicAdd(&g_count, 1u);
        s_is_last = (c == NB - 1) ? 1u : 0u;
    }
    __syncthreads();
    if (!s_is_last) return;

    // ---- last block: reduce 18 per-block partial vectors and emit loss ----
    for (int v = warp; v < 18; v += WPB) {
        float acc = 0.0f;
        #pragma unroll
        for (int j = 0; j < NBP / 32; j++)    // pads are zero
            acc += g_part[v * NBP + j * 32 + lane];
        #pragma unroll
        for (int off = 16; off > 0; off >>= 1)
            acc += __shfl_xor_sync(0xffffffffu, acc, off);
        if (lane == 0) totals[v] = (double)acc;
    }
    __syncthreads();
    if (tid == 0) {
        double ml = 0.0, mi = 0.0;
        for (int e = 0; e < EE; e++) { ml += totals[e]; mi += totals[9 + e]; }
        ml /= (double)EE; mi /= (double)EE;
        double vl = 0.0, vi = 0.0;
        for (int e = 0; e < EE; e++) {
            const double dl = totals[e] - ml;     vl += dl * dl;
            const double di = totals[9 + e] - mi; vi += di * di;
        }
        vl /= (double)(EE - 1); vi /= (double)(EE - 1);
        const double cvl = vl / (ml * ml + 1e-10);
        const double cvi = vi / (mi * mi + 1e-10);
        y_out[loss_idx] = (float)(0.01 * (cvi + cvl));
        g_count = 0;   // reset for next graph replay (deterministic)
    }
}

extern "C" void kernel_launch(void* const* d_in, const int* in_sizes, int n_in,
                              void* d_out, int out_size) {
    const int*   queries       = (const int*)  d_in[0];
    const int*   these_queries = (const int*)  d_in[1];
    const float* entity        = (const float*)d_in[2];
    const float* rel           = (const float*)d_in[3];
    const float* rel_diag      = (const float*)d_in[4];
    const float* bh            = (const float*)d_in[5];
    const float* bt            = (const float*)d_in[6];
    const float* c_param       = (const float*)d_in[7];
    const float* cnn_w         = (const float*)d_in[8];
    const float* cnn_b         = (const float*)d_in[9];
    const float* h2e_w         = (const float*)d_in[10];
    const float* h2e_b         = (const float*)d_in[11];
    const float* cnnn_w        = (const float*)d_in[12];
    const float* cnnn_b        = (const float*)d_in[13];
    const float* h2en_w        = (const float*)d_in[14];
    const float* h2en_b        = (const float*)d_in[15];
    const float* noise         = (const float*)d_in[16];
    float* out = (float*)d_out;

    swise_main_kernel<<<NB, 256>>>(
        queries, these_queries, entity, rel, rel_diag, bh, bt, c_param,
        cnn_w, cnn_b, h2e_w, h2e_b, cnnn_w, cnnn_b, h2en_w, h2en_b,
        noise, out, out_size - 1);
}

// round 7
// speedup vs baseline: 1.0858x; 1.0858x over previous
#include <cuda_runtime.h>
#include <math.h>

#define BB 32768
#define EE 9
#define RANKK 50
#define DD 450            // E*RANK
#define WPB 8             // warps per block
#define NB 592            // persistent grid: 148 SMs x 4 blocks
#define NBP 608           // padded partial stride (pad slots stay zero)
#define TOTW (NB * WPB)   // 4736 warps
#define XOFF 2            // head starts at sxw[2] so rel (sxw[452]) is 16B-aligned
#define XSZ 1352          // 2 + 450 + 900

// per-block partials: [v*NBP + block], v = 0..8 load, 9..17 importance
__device__ float g_part[18 * NBP];
__device__ unsigned int g_count = 0;

__device__ __forceinline__ float softplusf(float x) {
    if (x > 20.0f) return x;
    return log1pf(expf(x));
}
__device__ __forceinline__ float phif(float z) {
    return 0.5f * (1.0f + erff(z * 0.70710678118654752f));
}
__device__ __forceinline__ void cp_async8(unsigned int dst, const void* src) {
    asm volatile("cp.async.ca.shared.global [%0], [%1], 8;" :: "r"(dst), "l"(src));
}
__device__ __forceinline__ void cp_async16(unsigned int dst, const void* src) {
    asm volatile("cp.async.ca.shared.global [%0], [%1], 16;" :: "r"(dst), "l"(src));
}
__device__ __forceinline__ void cp_async_wait_all() {
    asm volatile("cp.async.commit_group;\n\tcp.async.wait_group 0;" ::: "memory");
}

__global__ __launch_bounds__(256, 4) void swise_main_kernel(
    const int* __restrict__ queries, const int* __restrict__ these_queries,
    const float* __restrict__ entity, const float* __restrict__ rel,
    const float* __restrict__ rel_diag,
    const float* __restrict__ bh, const float* __restrict__ bt,
    const float* __restrict__ c_param,
    const float* __restrict__ cnn_w, const float* __restrict__ cnn_b,
    const float* __restrict__ h2e_w, const float* __restrict__ h2e_b,
    const float* __restrict__ cnnn_w, const float* __restrict__ cnnn_b,
    const float* __restrict__ h2en_w, const float* __restrict__ h2en_b,
    const float* __restrict__ noise, float* __restrict__ y_out, int loss_idx)
{
    __shared__ __align__(16) float sx[WPB][XSZ];   // x image per warp, contiguous
    __shared__ float swc[25], swn[25];
    __shared__ __align__(16) float sh2e[EE * 128];
    __shared__ __align__(16) float sh2en[EE * 128];
    __shared__ float sbc[2];
    __shared__ float sbe[EE], sben[EE];
    __shared__ float s_load[EE], s_imp[EE];
    __shared__ unsigned int s_is_last;
    __shared__ double totals[18];

    const int tid = threadIdx.x;
    for (int i = tid; i < 25; i += blockDim.x) { swc[i] = cnn_w[i]; swn[i] = cnnn_w[i]; }
    for (int i = tid; i < EE * 128; i += blockDim.x) { sh2e[i] = h2e_w[i]; sh2en[i] = h2en_w[i]; }
    if (tid == 0) { sbc[0] = cnn_b[0]; sbc[1] = cnnn_b[0]; }
    if (tid < EE) { sbe[tid] = h2e_b[tid]; sben[tid] = h2en_b[tid];
                    s_load[tid] = 0.0f; s_imp[tid] = 0.0f; }
    __syncthreads();

    const int warp = tid >> 5, lane = tid & 31;
    const int ly = lane >> 2;          // oh  (0..7)
    const int lx = lane & 3;           // ow group (0..3), ow = 4*lx + q
    float* sxw = sx[warp];
    const unsigned int sxw_u32 =
        (unsigned int)__cvta_generic_to_shared(sxw);
    const int gw = blockIdx.x * WPB + warp;

    for (int b = gw; b < BB; b += TOTW) {
        const int q0 = queries[3 * b];
        const int q1 = queries[3 * b + 1];
        const int t2 = these_queries[3 * b + 2];

        __syncwarp();   // WAR: previous iteration's reads of sxw done

        // ---- stage x = [head | rel] via cp.async (no register round-trip) ----
        const float2* hrow = (const float2*)(entity + (size_t)q0 * DD);
        const float4* rrow = (const float4*)(rel + (size_t)q1 * (2 * DD));
        #pragma unroll
        for (int t = 0; t < 7; t++) {
            const int i = lane + 32 * t;
            cp_async8(sxw_u32 + 4 * (XOFF + 2 * i), hrow + i);
            cp_async16(sxw_u32 + 4 * (XOFF + DD + 4 * i), rrow + i);
        }
        if (lane == 0) {    // i = 224 tail
            cp_async8(sxw_u32 + 4 * (XOFF + 2 * 224), hrow + 224);
            cp_async16(sxw_u32 + 4 * (XOFF + DD + 4 * 224), rrow + 224);
        }
        cp_async_wait_all();
        __syncwarp();

        // ---- conv (stride 3, VALID): each lane computes 4 consecutive ow ----
        float accc[4] = {0.f, 0.f, 0.f, 0.f};
        float accn[4] = {0.f, 0.f, 0.f, 0.f};
        #pragma unroll
        for (int kh = 0; kh < 5; kh++) {
            const float* rp = sxw + XOFF + (3 * ly + kh) * RANKK + 12 * lx;
            float row[14];
            #pragma unroll
            for (int j2 = 0; j2 < 7; j2++) {
                const float2 t = *(const float2*)(rp + 2 * j2);
                row[2 * j2] = t.x; row[2 * j2 + 1] = t.y;
            }
            #pragma unroll
            for (int kw = 0; kw < 5; kw++) {
                const float wc = swc[kh * 5 + kw], wn = swn[kh * 5 + kw];
                #pragma unroll
                for (int q = 0; q < 4; q++) {
                    const float xv = row[3 * q + kw];
                    accc[q] = fmaf(xv, wc, accc[q]);
                    accn[q] = fmaf(xv, wn, accn[q]);
                }
            }
        }
        #pragma unroll
        for (int q = 0; q < 4; q++) { accc[q] += sbc[0]; accn[q] += sbc[1]; }

        // ---- fused linear: float4 weight loads, f_base = 16*ly + 4*lx ----
        const int f_base = 16 * ly + 4 * lx;
        float clean[EE], stdv[EE];
        #pragma unroll
        for (int e = 0; e < EE; e++) {
            const float4 wc4 = *(const float4*)&sh2e[e * 128 + f_base];
            const float4 wn4 = *(const float4*)&sh2en[e * 128 + f_base];
            float c0 = accc[0] * wc4.x; c0 = fmaf(accc[1], wc4.y, c0);
            c0 = fmaf(accc[2], wc4.z, c0); c0 = fmaf(accc[3], wc4.w, c0);
            float n0 = accn[0] * wn4.x; n0 = fmaf(accn[1], wn4.y, n0);
            n0 = fmaf(accn[2], wn4.z, n0); n0 = fmaf(accn[3], wn4.w, n0);
            clean[e] = c0; stdv[e] = n0;
        }
        // ---- split butterfly: round 1 routes clean->lanes<16, stdv->lanes>=16 ----
        const bool lowh = (lane < 16);
        float val[EE];
        #pragma unroll
        for (int e = 0; e < EE; e++) {
            const float oc = __shfl_xor_sync(0xffffffffu, clean[e], 16);
            const float os = __shfl_xor_sync(0xffffffffu, stdv[e], 16);
            val[e] = lowh ? (clean[e] + oc) : (stdv[e] + os);
        }
        #pragma unroll
        for (int off = 8; off > 0; off >>= 1) {
            #pragma unroll
            for (int e = 0; e < EE; e++)
                val[e] += __shfl_xor_sync(0xffffffffu, val[e], off);
        }
        #pragma unroll
        for (int e = 0; e < EE; e++) {
            const float other = __shfl_xor_sync(0xffffffffu, val[e], 16);
            clean[e] = lowh ? val[e] : other;
            stdv[e]  = lowh ? other  : val[e];
        }

        // ---- gating (uniform across lanes) ----
        float noisyv[EE];
        #pragma unroll
        for (int e = 0; e < EE; e++) {
            clean[e] += sbe[e];
            stdv[e] = softplusf(stdv[e] + sben[e]) + 0.01f;
            noisyv[e] = fmaf(noise[(size_t)b * EE + e], stdv[e], clean[e]);
        }
        int i1 = 0; float v1 = noisyv[0];
        #pragma unroll
        for (int e = 1; e < EE; e++) if (noisyv[e] > v1) { v1 = noisyv[e]; i1 = e; }
        int i2 = -1; float v2 = -INFINITY;
        #pragma unroll
        for (int e = 0; e < EE; e++) if (e != i1 && noisyv[e] > v2) { v2 = noisyv[e]; i2 = e; }
        float v3 = -INFINITY;
        #pragma unroll
        for (int e = 0; e < EE; e++) if (e != i1 && e != i2 && noisyv[e] > v3) v3 = noisyv[e];

        const float t_e = expf(v2 - v1);
        const float g1 = 1.0f / (1.0f + t_e);
        const float g2 = t_e / (1.0f + t_e);

        // prob/load: one expert per lane (parallel erf, conflict-free atomics)
        if (lane < EE) {
            float ce = 0.0f, se = 1.0f, ne = 0.0f;
            #pragma unroll
            for (int e = 0; e < EE; e++)
                if (lane == e) { ce = clean[e]; se = stdv[e]; ne = noisyv[e]; }
            const float thr = (ne > v3) ? v3 : v2;
            atomicAdd(&s_load[lane], phif((ce - thr) / se));
        }
        if (lane == 0) {
            atomicAdd(&s_imp[i1], g1);
            if (g2 > 0.0f) atomicAdd(&s_imp[i2], g2);
        }

        // ---- Givens + distance, ONLY for experts i1 and i2 (50 pairs) ----
        const float* rd = rel_diag + (size_t)q1 * DD;
        const float* rh = entity + (size_t)t2 * DD;
        float dA = 0.0f, dB = 0.0f;    // d2[i1], d2[i2]

        {   // item 1: lanes 0..24 -> expert i1, lanes 25..31 -> expert i2
            const bool sel = lane < 25;
            const int e = sel ? i1 : i2;
            const int p = sel ? lane : lane - 25;
            const float2 r2 = __ldg((const float2*)(rd + e * RANKK) + p);
            const float2 h2v = __ldg((const float2*)(rh + e * RANKK) + p);
            const float inv = rsqrtf(fmaxf(r2.x * r2.x + r2.y * r2.y, 1e-30f));
            const float c0 = r2.x * inv, c1 = r2.y * inv;
            const float x0 = sxw[XOFF + e * RANKK + 2 * p];
            const float x1 = sxw[XOFF + e * RANKK + 2 * p + 1];
            const float rl0 = sxw[XOFF + DD + e * (2 * RANKK) + 2 * p];
            const float rl1 = sxw[XOFF + DD + e * (2 * RANKK) + 2 * p + 1];
            const float u0 = (c0 * x0 - c1 * x1) + rl0 - h2v.x;
            const float u1 = (c1 * x0 + c0 * x1) + rl1 - h2v.y;
            const float dd = fmaf(u0, u0, u1 * u1);
            if (sel) dA += dd; else dB += dd;
        }
        if (lane < 18) {  // item 2: expert i2, p = lane+7
            const int p = lane + 7;
            const int e = i2;
            const float2 r2 = __ldg((const float2*)(rd + e * RANKK) + p);
            const float2 h2v = __ldg((const float2*)(rh + e * RANKK) + p);
            const float inv = rsqrtf(fmaxf(r2.x * r2.x + r2.y * r2.y, 1e-30f));
            const float c0 = r2.x * inv, c1 = r2.y * inv;
            const float x0 = sxw[XOFF + e * RANKK + 2 * p];
            const float x1 = sxw[XOFF + e * RANKK + 2 * p + 1];
            const float rl0 = sxw[XOFF + DD + e * (2 * RANKK) + 2 * p];
            const float rl1 = sxw[XOFF + DD + e * (2 * RANKK) + 2 * p + 1];
            const float u0 = (c0 * x0 - c1 * x1) + rl0 - h2v.x;
            const float u1 = (c1 * x0 + c0 * x1) + rl1 - h2v.y;
            dB = fmaf(u0, u0, fmaf(u1, u1, dB));
        }
        #pragma unroll
        for (int off = 16; off > 0; off >>= 1) {
            dA += __shfl_xor_sync(0xffffffffu, dA, off);
            dB += __shfl_xor_sync(0xffffffffu, dB, off);
        }

        // ---- score + masked logsumexp (mask = top-2 gates > 0) ----
        if (lane == 0) {
            const float cc = softplusf(c_param[q1]);
            const float bsum = bh[q0] + bt[t2];
            const float sc1 = bsum - cc * dA;
            const float sc2 = bsum - cc * dB;
            float s = expf(sc1) + (g2 > 0.0f ? expf(sc2) : 0.0f);
            if (s == 0.0f) s = 2.220446049250313e-16f;
            y_out[b] = logf(s);
        }
    }

    __syncthreads();
    if (tid < EE)       g_part[tid * NBP + blockIdx.x] = s_load[tid];
    else if (tid < 18)  g_part[tid * NBP + blockIdx.x] = s_imp[tid - 9];
    __threadfence();
    if (tid == 0) {
        const unsigned int c = atomicAdd(&g_count, 1u);
        s_is_last = (c == NB - 1) ? 1u : 0u;
    }
    __syncthreads();
    if (!s_is_last) return;

    // ---- last block: reduce 18 per-block partial vectors and emit loss ----
    for (int v = warp; v < 18; v += WPB) {
        float acc = 0.0f;
        #pragma unroll
        for (int j = 0; j < NBP / 32; j++)    // pads are zero
            acc += g_part[v * NBP + j * 32 + lane];
        #pragma unroll
        for (int off = 16; off > 0; off >>= 1)
            acc += __shfl_xor_sync(0xffffffffu, acc, off);
        if (lane == 0) totals[v] = (double)acc;
    }
    __syncthreads();
    if (tid == 0) {
        double ml = 0.0, mi = 0.0;
        for (int e = 0; e < EE; e++) { ml += totals[e]; mi += totals[9 + e]; }
        ml /= (double)EE; mi /= (double)EE;
        double vl = 0.0, vi = 0.0;
        for (int e = 0; e < EE; e++) {
            const double dl = totals[e] - ml;     vl += dl * dl;
            const double di = totals[9 + e] - mi; vi += di * di;
        }
        vl /= (double)(EE - 1); vi /= (double)(EE - 1);
        const double cvl = vl / (ml * ml + 1e-10);
        const double cvi = vi / (mi * mi + 1e-10);
        y_out[loss_idx] = (float)(0.01 * (cvi + cvl));
        g_count = 0;   // reset for next graph replay (deterministic)
    }
}

extern "C" void kernel_launch(void* const* d_in, const int* in_sizes, int n_in,
                              void* d_out, int out_size) {
    const int*   queries       = (const int*)  d_in[0];
    const int*   these_queries = (const int*)  d_in[1];
    const float* entity        = (const float*)d_in[2];
    const float* rel           = (const float*)d_in[3];
    const float* rel_diag      = (const float*)d_in[4];
    const float* bh            = (const float*)d_in[5];
    const float* bt            = (const float*)d_in[6];
    const float* c_param       = (const float*)d_in[7];
    const float* cnn_w         = (const float*)d_in[8];
    const float* cnn_b         = (const float*)d_in[9];
    const float* h2e_w         = (const float*)d_in[10];
    const float* h2e_b         = (const float*)d_in[11];
    const float* cnnn_w        = (const float*)d_in[12];
    const float* cnnn_b        = (const float*)d_in[13];
    const float* h2en_w        = (const float*)d_in[14];
    const float* h2en_b        = (const float*)d_in[15];
    const float* noise         = (const float*)d_in[16];
    float* out = (float*)d_out;

    swise_main_kernel<<<NB, 256>>>(
        queries, these_queries, entity, rel, rel_diag, bh, bt, c_param,
        cnn_w, cnn_b, h2e_w, h2e_b, cnnn_w, cnnn_b, h2en_w, h2en_b,
        noise, out, out_size - 1);
}